// round 17
// baseline (speedup 1.0000x reference)
#include <cuda_runtime.h>
#include <math.h>

#define NB 16
#define HW 3136
#define CC 256
#define OH 224
#define OW 224
#define RR 16
#define KS 33
#define NOUT (NB*OH*OW)

__device__ float g_mask56[NB * HW];

// ---------------------------------------------------------------------------
// One fully-unrolled segment of the padded triangular schedule (R16 winner).
// Per slot: mask B (triangular weight, hoisted dw), cvt, ring prefetch of
// slot kt+4 into registers via __ldcs (evict-first streaming), LDS.128 A
// fragment, 1 MMA. All addressing compile-time after unroll.
// ---------------------------------------------------------------------------
template <int NT, int SEGLEN>
__device__ __forceinline__ void run_segment(
    const float* seg_base, const float* next_base, const uint4* sdA,
    int j, float dw0, float dw1, int lane,
    float* r0, float* r1, float* c0, float* c1, float* c2, float* c3) {
#pragma unroll
  for (int kt = 0; kt < SEGLEN; kt++) {
    const int u = kt & 3;
    float b0 = r0[u], b1 = r1[u];
    const float* np = (kt + 4 < SEGLEN)
                          ? (seg_base + (kt + 4) * (8 * CC))
                          : (next_base + (kt + 4 - SEGLEN) * (8 * CC));
    r0[u] = __ldcs(np);
    r1[u] = __ldcs(np + 4 * CC);
    const float s0 = (kt < j) ? 1.f : ((kt == j) ? dw0 : 0.f);
    const float s1 = (kt < j) ? 1.f : ((kt == j) ? dw1 : 0.f);
    b0 *= s0;
    b1 *= s1;
    unsigned bh0, bh1;
    asm("cvt.rna.tf32.f32 %0, %1;" : "=r"(bh0) : "f"(b0));
    asm("cvt.rna.tf32.f32 %0, %1;" : "=r"(bh1) : "f"(b1));
    const uint4 a = sdA[kt * 32 + lane];
    asm("mma.sync.aligned.m16n8k8.row.col.f32.tf32.tf32.f32 "
        "{%0,%1,%2,%3}, {%4,%5,%6,%7}, {%8,%9}, {%0,%1,%2,%3};"
        : "+f"(c0[NT]), "+f"(c1[NT]), "+f"(c2[NT]), "+f"(c3[NT])
        : "r"(a.x), "r"(a.y), "r"(a.z), "r"(a.w), "r"(bh0), "r"(bh1));
  }
}

// ---------------------------------------------------------------------------
// Kernel 1: per-pixel Mahalanobis via tensor cores + symmetry (R16 winner,
// unchanged except: block 0 zeroes the score outputs so the fused blur
// kernel's atomicMax starts clean). quad = 2 * sum (diag weight 1/2).
// ---------------------------------------------------------------------------
__global__ __launch_bounds__(256, 4) void maha_kernel(
    const float* __restrict__ x, const float* __restrict__ mean,
    const float* __restrict__ M, float* __restrict__ score) {
  const int p = blockIdx.x;
  const int t = threadIdx.x;
  const int wid = t >> 5, lane = t & 31;
  const int tq = lane & 3;
  const int tr = lane >> 2;
  __shared__ float sd[CC][NB];
  __shared__ uint4 sdA[32 * 32];
  __shared__ float red[8][NB];

  if (p == 0 && t < NB) score[t] = 0.0f;

  {
    const float mu = mean[p * CC + t];
    const float* xp = x + (size_t)p * CC + t;
#pragma unroll
    for (int b = 0; b < NB; b++)
      sd[t][b] = xp[(size_t)b * ((size_t)HW * CC)] - mu;
  }
  __syncthreads();

#pragma unroll
  for (int s2 = 0; s2 < 4; s2++) {
    const int kt = wid + s2 * 8;
    unsigned x0, x1, x2, x3;
    asm("cvt.rna.tf32.f32 %0, %1;" : "=r"(x0) : "f"(sd[kt * 8 + tq][tr]));
    asm("cvt.rna.tf32.f32 %0, %1;" : "=r"(x1) : "f"(sd[kt * 8 + tq][tr + 8]));
    asm("cvt.rna.tf32.f32 %0, %1;" : "=r"(x2) : "f"(sd[kt * 8 + tq + 4][tr]));
    asm("cvt.rna.tf32.f32 %0, %1;" : "=r"(x3) : "f"(sd[kt * 8 + tq + 4][tr + 8]));
    sdA[kt * 32 + lane] = make_uint4(x0, x1, x2, x3);
  }
  __syncthreads();

  const float* Mp = M + ((size_t)p << 16);
  const int w = wid;

  const float dw0 = (tq < tr) ? 1.f : (tq == tr) ? 0.5f : 0.f;
  const float dw1 = (tq + 4 < tr) ? 1.f : (tq + 4 == tr) ? 0.5f : 0.f;

  const float* tb = Mp + tq * CC + tr;
  const float* sb0 = tb + w * 8;
  const float* sb1 = tb + (15 - w) * 8;
  const float* sb2 = tb + (16 + w) * 8;
  const float* sb3 = tb + (31 - w) * 8;

  float c0[4], c1[4], c2[4], c3[4];
#pragma unroll
  for (int nt = 0; nt < 4; nt++) { c0[nt] = c1[nt] = c2[nt] = c3[nt] = 0.f; }

  float r0[4], r1[4];
#pragma unroll
  for (int u = 0; u < 4; u++) {
    const float* ptr = sb0 + u * (8 * CC);
    r0[u] = __ldcs(ptr);
    r1[u] = __ldcs(ptr + 4 * CC);
  }

  run_segment<0, 8>(sb0, sb1, sdA, w, dw0, dw1, lane, r0, r1, c0, c1, c2, c3);
  run_segment<1, 16>(sb1, sb2, sdA, 15 - w, dw0, dw1, lane, r0, r1, c0, c1, c2, c3);
  run_segment<2, 24>(sb2, sb3, sdA, 16 + w, dw0, dw1, lane, r0, r1, c0, c1, c2, c3);
  run_segment<3, 32>(sb3, sb3, sdA, 31 - w, dw0, dw1, lane, r0, r1, c0, c1, c2, c3);

  const int jl[4] = {w, 15 - w, 16 + w, 31 - w};
  float q0 = 0.f, q1 = 0.f;
#pragma unroll
  for (int nt = 0; nt < 4; nt++) {
    const int n = jl[nt] * 8 + tq * 2;
    q0 += c0[nt] * sd[n][tr]     + c1[nt] * sd[n + 1][tr];
    q1 += c2[nt] * sd[n][tr + 8] + c3[nt] * sd[n + 1][tr + 8];
  }
  q0 += __shfl_xor_sync(0xffffffffu, q0, 1);
  q0 += __shfl_xor_sync(0xffffffffu, q0, 2);
  q1 += __shfl_xor_sync(0xffffffffu, q1, 1);
  q1 += __shfl_xor_sync(0xffffffffu, q1, 2);
  if (tq == 0) {
    red[wid][tr] = q0;
    red[wid][tr + 8] = q1;
  }
  __syncthreads();
  if (t < NB) {
    float s = 0.f;
#pragma unroll
    for (int ww = 0; ww < 8; ww++) s += red[ww][t];
    g_mask56[t * HW + p] = sqrtf(fmaxf(2.0f * s, 0.f));
  }
}

__device__ __forceinline__ int reflect101(int i) {
  if (i < 0) i = -i;
  if (i > 223) i = 446 - i;
  return i;
}

// ---------------------------------------------------------------------------
// Kernel 2: FUSED resize (56->224 bilinear) + vertical blur + horizontal
// blur + per-batch max, one 32x32 output tile per block (grid 16*49).
// The 56x56 mask is L1/L2-resident, so each block re-derives its 64x64
// resized halo directly (reflect-101 applied in OUTPUT space before
// sampling == separable blur on the resized image). s1: 64x64 resized halo;
// s2: 32x64 vertically blurred strip; final: 32x32 outputs + atomicMax.
// ---------------------------------------------------------------------------
__global__ __launch_bounds__(256) void blur_fused_kernel(
    float* __restrict__ out_mask, float* __restrict__ score) {
  __shared__ float s1[64][64];   // 16 KB
  __shared__ float s2[32][64];   //  8 KB
  __shared__ float w[KS];
  __shared__ float inv;
  __shared__ float smx[8];
  const int tid = threadIdx.x;
  if (tid < KS) {
    const float d = (float)(tid - RR);
    w[tid] = expf(-(d * d) / 32.0f);
  }
  __syncthreads();
  if (tid == 0) {
    float s = 0.f;
    for (int j = 0; j < KS; j++) s += w[j];
    inv = 1.0f / s;
  }

  const int b = blockIdx.x / 49;
  const int tile = blockIdx.x % 49;
  const int ty = (tile / 7) * 32;
  const int tx = (tile % 7) * 32;
  const float* mp = g_mask56 + b * HW;

  // stage s1: resized halo rows ty-16..ty+47, cols tx-16..tx+47 (reflected)
#pragma unroll
  for (int li = tid; li < 64 * 64; li += 256) {
    const int r = li >> 6, c = li & 63;
    const int gy = reflect101(ty + r - RR);
    const int gx = reflect101(tx + c - RR);
    const float fy = (gy + 0.5f) * 0.25f - 0.5f;
    const float fx = (gx + 0.5f) * 0.25f - 0.5f;
    const int y0 = (int)floorf(fy);
    const int x0 = (int)floorf(fx);
    const float wy = fy - (float)y0;
    const float wx = fx - (float)x0;
    const int y0c = min(max(y0, 0), 55), y1c = min(max(y0 + 1, 0), 55);
    const int x0c = min(max(x0, 0), 55), x1c = min(max(x0 + 1, 0), 55);
    const float v00 = mp[y0c * 56 + x0c];
    const float v01 = mp[y0c * 56 + x1c];
    const float v10 = mp[y1c * 56 + x0c];
    const float v11 = mp[y1c * 56 + x1c];
    s1[r][c] = (1.f - wy) * ((1.f - wx) * v00 + wx * v01) +
               wy * ((1.f - wx) * v10 + wx * v11);
  }
  __syncthreads();

  // vertical blur: 32 rows x 64 cols
#pragma unroll
  for (int li = tid; li < 32 * 64; li += 256) {
    const int r = li >> 6, c = li & 63;
    float sum = 0.f;
#pragma unroll
    for (int j = 0; j < KS; j++) sum += w[j] * s1[r + j][c];
    s2[r][c] = sum * inv;
  }
  __syncthreads();

  // horizontal blur + max: 32 x 32 outputs
  float mx = 0.f;
  float* dst = out_mask + (b * OH + ty) * OW + tx;
#pragma unroll
  for (int li = tid; li < 32 * 32; li += 256) {
    const int r = li >> 5, c = li & 31;
    float sum = 0.f;
#pragma unroll
    for (int j = 0; j < KS; j++) sum += w[j] * s2[r][c + j];
    sum *= inv;
    dst[r * OW + c] = sum;
    mx = fmaxf(mx, sum);
  }
#pragma unroll
  for (int off = 16; off > 0; off >>= 1)
    mx = fmaxf(mx, __shfl_down_sync(0xffffffffu, mx, off));
  if ((tid & 31) == 0) smx[tid >> 5] = mx;
  __syncthreads();
  if (tid == 0) {
    float m2 = smx[0];
#pragma unroll
    for (int k = 1; k < 8; k++) m2 = fmaxf(m2, smx[k]);
    // values are >= 0, so int compare on the bits is order-preserving
    atomicMax((int*)&score[b], __float_as_int(m2));
  }
}

extern "C" void kernel_launch(void* const* d_in, const int* in_sizes, int n_in,
                              void* d_out, int out_size) {
  const float* inputs = (const float*)d_in[0];    // [16,56,56,256]
  const float* mean = (const float*)d_in[1];      // [3136,256]
  const float* cvar_inv = (const float*)d_in[2];  // [3136,256,256]
  float* out = (float*)d_out;
  float* score = out;          // [16,1]
  float* mask = out + NB;      // [16,224,224,1]

  maha_kernel<<<HW, 256>>>(inputs, mean, cvar_inv, score);
  blur_fused_kernel<<<NB * 49, 256>>>(mask, score);
}